// round 15
// baseline (speedup 1.0000x reference)
#include <cuda_runtime.h>
#include <math.h>
#include <stdint.h>

#define EMB 1024
#define SEQ 1024
#define NB 8
#define HEADS 16
#define HD 64
#define ROWS (NB * SEQ)                  // 8192
#define OUT_ELEMS ((size_t)ROWS * EMB)   // 8388608
#define SROW 20                          // smem words per row (80B, 16B-aligned)

// Scratch (static device globals; no runtime allocation allowed)
__device__ float g_Q[ROWS * EMB];
__device__ float g_K[ROWS * EMB];
__device__ float g_V[ROWS * EMB];
__device__ float g_O[ROWS * EMB];

// ---------------------------------------------------------------------------
// helpers
// ---------------------------------------------------------------------------
__device__ __forceinline__ unsigned f2tf(float x) {
    unsigned r;
    asm("cvt.rna.tf32.f32 %0, %1;" : "=r"(r) : "f"(x));
    return r;
}

__device__ __forceinline__ void mma_tf32(float* c, const unsigned* a, const unsigned* b) {
    asm volatile(
        "mma.sync.aligned.m16n8k8.row.col.f32.tf32.tf32.f32 "
        "{%0,%1,%2,%3},{%4,%5,%6,%7},{%8,%9},{%0,%1,%2,%3};\n"
        : "+f"(c[0]), "+f"(c[1]), "+f"(c[2]), "+f"(c[3])
        : "r"(a[0]), "r"(a[1]), "r"(a[2]), "r"(a[3]),
          "r"(b[0]), "r"(b[1]));
}

__device__ __forceinline__ uint32_t smem_u32(const void* p) {
    uint32_t a;
    asm("{ .reg .u64 t; cvta.to.shared.u64 t, %1; cvt.u32.u64 %0, t; }"
        : "=r"(a) : "l"(p));
    return a;
}

__device__ __forceinline__ void ldsm4(unsigned& r0, unsigned& r1, unsigned& r2,
                                      unsigned& r3, uint32_t addr) {
    asm volatile("ldmatrix.sync.aligned.m8n8.x4.shared.b16 {%0,%1,%2,%3}, [%4];"
                 : "=r"(r0), "=r"(r1), "=r"(r2), "=r"(r3) : "r"(addr));
}

// byte offset of the 16B chunk jc (tf32 cols jc*4..jc*4+3) of row `row`
__device__ __forceinline__ uint32_t frag_off(int row, int jc) {
    const int chunk = jc ^ ((row >> 3) & 3);
    return (uint32_t)((row * SROW + chunk * 4) * 4);
}

// ---------------------------------------------------------------------------
// NT GEMM: C = alpha * A(row-major,lda) @ B(row-major,ldb)^T + bias
// CTA 128x128, 256 thr (8 warps 2x4), warp tile 64x32, BK=16 double-buffered.
// smem row-major [row][k] (stride SROW, XOR 16B-chunk swizzle); ldmatrix frags.
// ---------------------------------------------------------------------------
template <int KDIM>
__device__ __forceinline__ void gemm_nt_body(
    const float* __restrict__ A, int lda,
    const float* __restrict__ B, int ldb,
    float* __restrict__ C, int ldc,
    float alpha, const float* __restrict__ bias)
{
    __shared__ unsigned As[2][128 * SROW];
    __shared__ unsigned Bs[2][128 * SROW];

    const int tid  = threadIdx.x;
    const int m0   = blockIdx.y * 128;
    const int n0   = blockIdx.x * 128;
    const int warp = tid >> 5;
    const int lane = tid & 31;
    const int wr   = (warp >> 2) * 64;   // 2 m-blocks
    const int wc   = (warp & 3) * 32;    // 4 n-blocks
    const int g    = lane >> 2;
    const int t    = lane & 3;

    const uint32_t abase[2] = { smem_u32(&As[0][0]), smem_u32(&As[1][0]) };
    const uint32_t bbase[2] = { smem_u32(&Bs[0][0]), smem_u32(&Bs[1][0]) };

    const int lrow8 = ((lane >> 3) & 1) * 8 + (lane & 7);
    const int ljc   = lane >> 4;
    uint32_t aoff[2][4], boff[2][2];
#pragma unroll
    for (int kkc = 0; kkc < 2; kkc++) {
#pragma unroll
        for (int i = 0; i < 4; i++)
            aoff[kkc][i] = frag_off(wr + i * 16 + lrow8, kkc * 2 + ljc);
#pragma unroll
        for (int p = 0; p < 2; p++)
            boff[kkc][p] = frag_off(wc + p * 16 + lrow8, kkc * 2 + ljc);
    }

    float acc[4][4][4] = {};

    const int srow = tid & 127;          // staging row
    const int kh   = tid >> 7;           // k-half (0/1)
    const float* Ap = A + (size_t)(m0 + srow) * lda + kh * 8;
    const float* Bp = B + (size_t)(n0 + srow) * ldb + kh * 8;
    const int schunkx = (srow >> 3) & 3;

    float4 av[2], bv[2];
    auto ldtile = [&](int kt) {
        av[0] = *(const float4*)(Ap + kt * 16);
        av[1] = *(const float4*)(Ap + kt * 16 + 4);
        bv[0] = *(const float4*)(Bp + kt * 16);
        bv[1] = *(const float4*)(Bp + kt * 16 + 4);
    };
    auto sttile = [&](int buf) {
#pragma unroll
        for (int j2 = 0; j2 < 2; j2++) {
            const int chunk = (kh * 2 + j2) ^ schunkx;
            uint4 at = make_uint4(f2tf(av[j2].x), f2tf(av[j2].y), f2tf(av[j2].z), f2tf(av[j2].w));
            uint4 bt = make_uint4(f2tf(bv[j2].x), f2tf(bv[j2].y), f2tf(bv[j2].z), f2tf(bv[j2].w));
            *(uint4*)&As[buf][srow * SROW + chunk * 4] = at;
            *(uint4*)&Bs[buf][srow * SROW + chunk * 4] = bt;
        }
    };

    ldtile(0);
    sttile(0);
    __syncthreads();

    const int NT = KDIM / 16;
#pragma unroll 1
    for (int kt = 0; kt < NT; kt++) {
        const int buf = kt & 1;
        if (kt + 1 < NT) ldtile(kt + 1);

#pragma unroll
        for (int kkc = 0; kkc < 2; kkc++) {
            unsigned af[4][4], bf[4][2];
#pragma unroll
            for (int mi = 0; mi < 4; mi++)
                ldsm4(af[mi][0], af[mi][1], af[mi][2], af[mi][3],
                      abase[buf] + aoff[kkc][mi]);
#pragma unroll
            for (int p = 0; p < 2; p++) {
                unsigned r0, r1, r2, r3;
                ldsm4(r0, r1, r2, r3, bbase[buf] + boff[kkc][p]);
                bf[2 * p][0] = r0; bf[2 * p + 1][0] = r1;
                bf[2 * p][1] = r2; bf[2 * p + 1][1] = r3;
            }
#pragma unroll
            for (int mi = 0; mi < 4; mi++)
#pragma unroll
                for (int ni = 0; ni < 4; ni++)
                    mma_tf32(acc[mi][ni], af[mi], bf[ni]);
        }

        if (kt + 1 < NT) sttile(buf ^ 1);
        __syncthreads();
    }

#pragma unroll
    for (int mi = 0; mi < 4; mi++) {
#pragma unroll
        for (int ni = 0; ni < 4; ni++) {
            const int row = m0 + wr + mi * 16 + g;
            const int col = n0 + wc + ni * 8 + t * 2;
            float b0 = 0.f, b1 = 0.f;
            if (bias) { b0 = bias[col]; b1 = bias[col + 1]; }
            *(float2*)&C[(size_t)row * ldc + col] =
                make_float2(acc[mi][ni][0] * alpha + b0, acc[mi][ni][1] * alpha + b1);
            *(float2*)&C[(size_t)(row + 8) * ldc + col] =
                make_float2(acc[mi][ni][2] * alpha + b0, acc[mi][ni][3] * alpha + b1);
        }
    }
}

// Fused Q/K/V projections: grid.z selects which GEMM.
__global__ __launch_bounds__(256, 2) void qkv_proj(
    const float* __restrict__ query, const float* __restrict__ key_,
    const float* __restrict__ value,
    const float* __restrict__ Wq, const float* __restrict__ Wk,
    const float* __restrict__ Wv)
{
    const int z = blockIdx.z;
    const float* A = (z == 0) ? query : (z == 1) ? key_ : value;
    const float* W = (z == 0) ? Wq : (z == 1) ? Wk : Wv;
    float* C = (z == 0) ? g_Q : (z == 1) ? g_K : g_V;
    gemm_nt_body<EMB>(A, EMB, W, EMB, C, EMB, 1.0f, nullptr);
}

__global__ __launch_bounds__(256, 2) void proj_tf32(
    const float* __restrict__ A, const float* __restrict__ B,
    float* __restrict__ C, const float* __restrict__ bias)
{
    gemm_nt_body<EMB>(A, EMB, B, EMB, C, EMB, 1.0f, bias);
}

__global__ __launch_bounds__(256, 2) void energy_tf32(float* __restrict__ att)
{
    const int z = blockIdx.z;
    const int n = z >> 4, h = z & 15;
    gemm_nt_body<HD>(g_Q + (size_t)n * SEQ * EMB + h * HD, EMB,
                     g_K + (size_t)n * SEQ * EMB + h * HD, EMB,
                     att + (size_t)z * SEQ * SEQ, SEQ, 0.125f, nullptr);
}

// ---------------------------------------------------------------------------
// Row softmax over last dim (1024), in place, with mask[n,k] (-1e20 where 0).
// ---------------------------------------------------------------------------
__global__ __launch_bounds__(256) void softmax_kernel(
    float* __restrict__ att, const int* __restrict__ mask)
{
    __shared__ float sbuf[8];
    const int row = blockIdx.x;
    const int n = row >> 14;
    float* p = att + (size_t)row * SEQ;
    const int c = threadIdx.x * 4;
    const int* mrow = mask + n * SEQ;

    float4 x = *(const float4*)(p + c);
    if (mrow[c + 0] == 0) x.x = -1e20f;
    if (mrow[c + 1] == 0) x.y = -1e20f;
    if (mrow[c + 2] == 0) x.z = -1e20f;
    if (mrow[c + 3] == 0) x.w = -1e20f;

    float m = fmaxf(fmaxf(x.x, x.y), fmaxf(x.z, x.w));
#pragma unroll
    for (int o = 16; o; o >>= 1) m = fmaxf(m, __shfl_xor_sync(0xffffffffu, m, o));
    if ((threadIdx.x & 31) == 0) sbuf[threadIdx.x >> 5] = m;
    __syncthreads();
    m = sbuf[0];
#pragma unroll
    for (int i = 1; i < 8; i++) m = fmaxf(m, sbuf[i]);

    float4 e;
    e.x = __expf(x.x - m);
    e.y = __expf(x.y - m);
    e.z = __expf(x.z - m);
    e.w = __expf(x.w - m);
    float s = (e.x + e.y) + (e.z + e.w);
#pragma unroll
    for (int o = 16; o; o >>= 1) s += __shfl_xor_sync(0xffffffffu, s, o);
    __syncthreads();
    if ((threadIdx.x & 31) == 0) sbuf[threadIdx.x >> 5] = s;
    __syncthreads();
    s = 0.f;
#pragma unroll
    for (int i = 0; i < 8; i++) s += sbuf[i];

    const float inv = 1.0f / s;
    e.x *= inv; e.y *= inv; e.z *= inv; e.w *= inv;
    *(float4*)(p + c) = e;
}

// ---------------------------------------------------------------------------
// att*V (NN): per z = n*16+h,  C[1024,64] = P[1024,1024] @ V[1024,64]
// CTA 128x64, 256 thr (8 warps 4x2), warp tile 32x32, BK=16 double-buffered.
// A staged [q][k]; V transposed into [n][k] at staging (ldmatrix B frags).
// ---------------------------------------------------------------------------
__global__ __launch_bounds__(256, 2) void attv_tf32(const float* __restrict__ att)
{
    const int z = blockIdx.z;
    const int n = z >> 4, h = z & 15;
    const float* A = att + (size_t)z * SEQ * SEQ;
    const float* B = g_V + (size_t)n * SEQ * EMB + h * HD;
    float* C = g_O + (size_t)n * SEQ * EMB + h * HD;

    __shared__ unsigned As[2][128 * SROW];
    __shared__ unsigned Bs[2][64 * SROW];

    const int tid  = threadIdx.x;
    const int m0   = blockIdx.y * 128;
    const int warp = tid >> 5;
    const int lane = tid & 31;
    const int wr   = (warp >> 1) * 32;   // 4 m-blocks
    const int wc   = (warp & 1) * 32;    // 2 n-blocks
    const int g    = lane >> 2;
    const int t    = lane & 3;

    const uint32_t abase[2] = { smem_u32(&As[0][0]), smem_u32(&As[1][0]) };
    const uint32_t bbase[2] = { smem_u32(&Bs[0][0]), smem_u32(&Bs[1][0]) };

    const int lrow8 = ((lane >> 3) & 1) * 8 + (lane & 7);
    const int ljc   = lane >> 4;
    uint32_t aoff[2][2], boff[2][2];
#pragma unroll
    for (int kkc = 0; kkc < 2; kkc++) {
#pragma unroll
        for (int i = 0; i < 2; i++)
            aoff[kkc][i] = frag_off(wr + i * 16 + lrow8, kkc * 2 + ljc);
#pragma unroll
        for (int p = 0; p < 2; p++)
            boff[kkc][p] = frag_off(wc + p * 16 + lrow8, kkc * 2 + ljc);
    }

    float acc[2][4][4] = {};

    const int srow = tid & 127;
    const int kh   = tid >> 7;
    const float* Ap = A + (size_t)(m0 + srow) * SEQ + kh * 8;
    const int schunkx = (srow >> 3) & 3;
    const int bk  = tid >> 4;            // 0..15 (k within ktile)
    const int bnc = (tid & 15) * 4;      // n col base

    float4 av[2], bvv;
    auto ldtile = [&](int kt) {
        av[0] = *(const float4*)(Ap + kt * 16);
        av[1] = *(const float4*)(Ap + kt * 16 + 4);
        bvv   = *(const float4*)(B + (size_t)(kt * 16 + bk) * EMB + bnc);
    };
    auto sttile = [&](int buf) {
#pragma unroll
        for (int j2 = 0; j2 < 2; j2++) {
            const int chunk = (kh * 2 + j2) ^ schunkx;
            uint4 at = make_uint4(f2tf(av[j2].x), f2tf(av[j2].y), f2tf(av[j2].z), f2tf(av[j2].w));
            *(uint4*)&As[buf][srow * SROW + chunk * 4] = at;
        }
        {
            const int jc = bk >> 2, kw = bk & 3;
            const float* v4 = (const float*)&bvv;
#pragma unroll
            for (int c = 0; c < 4; c++) {
                const int nrow = bnc + c;
                const int chunk = jc ^ ((nrow >> 3) & 3);
                Bs[buf][nrow * SROW + chunk * 4 + kw] = f2tf(v4[c]);
            }
        }
    };

    ldtile(0);
    sttile(0);
    __syncthreads();

    const int NT = SEQ / 16;
#pragma unroll 1
    for (int kt = 0; kt < NT; kt++) {
        const int buf = kt & 1;
        if (kt + 1 < NT) ldtile(kt + 1);

#pragma unroll
        for (int kkc = 0; kkc < 2; kkc++) {
            unsigned af[2][4], bf[4][2];
#pragma unroll
            for (int mi = 0; mi < 2; mi++)
                ldsm4(af[mi][0], af[mi][1], af[mi][2], af[mi][3],
                      abase[buf] + aoff[kkc][mi]);
#pragma unroll
            for (int p = 0; p < 2; p++) {
                unsigned r0, r1, r2, r3;
                ldsm4(r0, r1, r2, r3, bbase[buf] + boff[kkc][p]);
                bf[2 * p][0] = r0; bf[2 * p + 1][0] = r1;
                bf[2 * p][1] = r2; bf[2 * p + 1][1] = r3;
            }
#pragma unroll
            for (int mi = 0; mi < 2; mi++)
#pragma unroll
                for (int ni = 0; ni < 4; ni++)
                    mma_tf32(acc[mi][ni], af[mi], bf[ni]);
        }

        if (kt + 1 < NT) sttile(buf ^ 1);
        __syncthreads();
    }

#pragma unroll
    for (int mi = 0; mi < 2; mi++) {
#pragma unroll
        for (int ni = 0; ni < 4; ni++) {
            const int row = m0 + wr + mi * 16 + g;
            const int col = wc + ni * 8 + t * 2;
            *(float2*)&C[(size_t)row * EMB + col] =
                make_float2(acc[mi][ni][0], acc[mi][ni][1]);
            *(float2*)&C[(size_t)(row + 8) * EMB + col] =
                make_float2(acc[mi][ni][2], acc[mi][ni][3]);
        }
    }
}

// ---------------------------------------------------------------------------
extern "C" void kernel_launch(void* const* d_in, const int* in_sizes, int n_in,
                              void* d_out, int out_size)
{
    const float* value = (const float*)d_in[0];
    const float* key_  = (const float*)d_in[1];
    const float* query = (const float*)d_in[2];
    const int*   mask  = (const int*)d_in[3];
    const float* Wv    = (const float*)d_in[4];
    const float* Wk    = (const float*)d_in[5];
    const float* Wq    = (const float*)d_in[6];
    const float* Wo    = (const float*)d_in[7];
    const float* bo    = (const float*)d_in[8];

    float* out = (float*)d_out;                 // [8,1024,1024]
    float* att = out + OUT_ELEMS;               // [8,16,1024,1024]

    float* op;
    cudaGetSymbolAddress((void**)&op, g_O);

    dim3 blk(256);

    qkv_proj<<<dim3(EMB / 128, ROWS / 128, 3), blk>>>(query, key_, value, Wq, Wk, Wv);
    energy_tf32<<<dim3(SEQ / 128, SEQ / 128, NB * HEADS), blk>>>(att);
    softmax_kernel<<<NB * HEADS * SEQ, 256>>>(att, mask);
    attv_tf32<<<dim3(1, SEQ / 128, NB * HEADS), blk>>>(att);
    proj_tf32<<<dim3(EMB / 128, ROWS / 128), blk>>>(op, Wo, out, bo);
}

// round 16
// speedup vs baseline: 1.0598x; 1.0598x over previous
#include <cuda_runtime.h>
#include <math.h>
#include <stdint.h>

#define EMB 1024
#define SEQ 1024
#define NB 8
#define HEADS 16
#define HD 64
#define ROWS (NB * SEQ)                  // 8192
#define OUT_ELEMS ((size_t)ROWS * EMB)   // 8388608
#define SROW 20                          // smem words per row (80B, 16B-aligned)

// Scratch (static device globals; no runtime allocation allowed)
__device__ float g_Q[ROWS * EMB];
__device__ float g_K[ROWS * EMB];
__device__ float g_V[ROWS * EMB];
__device__ float g_O[ROWS * EMB];

// ---------------------------------------------------------------------------
// helpers
// ---------------------------------------------------------------------------
__device__ __forceinline__ unsigned f2tf(float x) {
    unsigned r;
    asm("cvt.rna.tf32.f32 %0, %1;" : "=r"(r) : "f"(x));
    return r;
}

__device__ __forceinline__ void mma_tf32(float* c, const unsigned* a, const unsigned* b) {
    asm volatile(
        "mma.sync.aligned.m16n8k8.row.col.f32.tf32.tf32.f32 "
        "{%0,%1,%2,%3},{%4,%5,%6,%7},{%8,%9},{%0,%1,%2,%3};\n"
        : "+f"(c[0]), "+f"(c[1]), "+f"(c[2]), "+f"(c[3])
        : "r"(a[0]), "r"(a[1]), "r"(a[2]), "r"(a[3]),
          "r"(b[0]), "r"(b[1]));
}

__device__ __forceinline__ uint32_t smem_u32(const void* p) {
    uint32_t a;
    asm("{ .reg .u64 t; cvta.to.shared.u64 t, %1; cvt.u32.u64 %0, t; }"
        : "=r"(a) : "l"(p));
    return a;
}

__device__ __forceinline__ void ldsm4(unsigned& r0, unsigned& r1, unsigned& r2,
                                      unsigned& r3, uint32_t addr) {
    asm volatile("ldmatrix.sync.aligned.m8n8.x4.shared.b16 {%0,%1,%2,%3}, [%4];"
                 : "=r"(r0), "=r"(r1), "=r"(r2), "=r"(r3) : "r"(addr));
}

// byte offset of the 16B chunk jc (tf32 cols jc*4..jc*4+3) of row `row`
__device__ __forceinline__ uint32_t frag_off(int row, int jc) {
    const int chunk = jc ^ ((row >> 3) & 3);
    return (uint32_t)((row * SROW + chunk * 4) * 4);
}

// ---------------------------------------------------------------------------
// NT GEMM: C = alpha * A(row-major,lda) @ B(row-major,ldb)^T + bias
// CTA 128x128, 128 thr (4 warps), warp tile 64x64, BK=16 double-buffered.
// smem row-major [row][k] (stride SROW, XOR 16B-chunk swizzle); fragments
// loaded with ldmatrix.x4 (conflict-free). STREAM=1 -> __stcs epilogue.
// ---------------------------------------------------------------------------
template <int KDIM, int STREAM>
__device__ __forceinline__ void gemm_nt_body(
    const float* __restrict__ A, int lda,
    const float* __restrict__ B, int ldb,
    float* __restrict__ C, int ldc,
    float alpha, const float* __restrict__ bias)
{
    __shared__ unsigned As[2][128 * SROW];
    __shared__ unsigned Bs[2][128 * SROW];

    const int tid  = threadIdx.x;
    const int m0   = blockIdx.y * 128;
    const int n0   = blockIdx.x * 128;
    const int warp = tid >> 5;
    const int lane = tid & 31;
    const int wr   = (warp >> 1) * 64;
    const int wc   = (warp & 1) * 64;
    const int g    = lane >> 2;
    const int t    = lane & 3;

    const uint32_t abase[2] = { smem_u32(&As[0][0]), smem_u32(&As[1][0]) };
    const uint32_t bbase[2] = { smem_u32(&Bs[0][0]), smem_u32(&Bs[1][0]) };

    // per-lane ldmatrix pointer offsets (loop-invariant)
    const int lrow8 = ((lane >> 3) & 1) * 8 + (lane & 7);
    const int ljc   = lane >> 4;                     // 0 or 1
    uint32_t aoff[2][4], boff[2][4];
#pragma unroll
    for (int kkc = 0; kkc < 2; kkc++)
#pragma unroll
        for (int i = 0; i < 4; i++) {
            aoff[kkc][i] = frag_off(wr + i * 16 + lrow8, kkc * 2 + ljc);
            boff[kkc][i] = frag_off(wc + i * 16 + lrow8, kkc * 2 + ljc);
        }

    float acc[4][8][4] = {};

    const int srow = tid;                            // staging row 0..127
    const float* Ap = A + (size_t)(m0 + srow) * lda;
    const float* Bp = B + (size_t)(n0 + srow) * ldb;
    const int schunkx = (srow >> 3) & 3;

    float4 av[4], bv[4];
    auto ldtile = [&](int kt) {
#pragma unroll
        for (int j = 0; j < 4; j++) {
            av[j] = *(const float4*)(Ap + kt * 16 + j * 4);
            bv[j] = *(const float4*)(Bp + kt * 16 + j * 4);
        }
    };
    auto sttile = [&](int buf) {
#pragma unroll
        for (int j = 0; j < 4; j++) {
            const int chunk = j ^ schunkx;
            uint4 at = make_uint4(f2tf(av[j].x), f2tf(av[j].y), f2tf(av[j].z), f2tf(av[j].w));
            uint4 bt = make_uint4(f2tf(bv[j].x), f2tf(bv[j].y), f2tf(bv[j].z), f2tf(bv[j].w));
            *(uint4*)&As[buf][srow * SROW + chunk * 4] = at;
            *(uint4*)&Bs[buf][srow * SROW + chunk * 4] = bt;
        }
    };

    ldtile(0);
    sttile(0);
    __syncthreads();

    const int NT = KDIM / 16;
#pragma unroll 1
    for (int kt = 0; kt < NT; kt++) {
        const int buf = kt & 1;
        if (kt + 1 < NT) ldtile(kt + 1);

#pragma unroll
        for (int kkc = 0; kkc < 2; kkc++) {
            unsigned af[4][4], bf[8][2];
#pragma unroll
            for (int mi = 0; mi < 4; mi++)
                ldsm4(af[mi][0], af[mi][1], af[mi][2], af[mi][3],
                      abase[buf] + aoff[kkc][mi]);
#pragma unroll
            for (int p = 0; p < 4; p++) {
                unsigned r0, r1, r2, r3;
                ldsm4(r0, r1, r2, r3, bbase[buf] + boff[kkc][p]);
                bf[2 * p][0] = r0; bf[2 * p + 1][0] = r1;
                bf[2 * p][1] = r2; bf[2 * p + 1][1] = r3;
            }
#pragma unroll
            for (int mi = 0; mi < 4; mi++)
#pragma unroll
                for (int ni = 0; ni < 8; ni++)
                    mma_tf32(acc[mi][ni], af[mi], bf[ni]);
        }

        if (kt + 1 < NT) sttile(buf ^ 1);
        __syncthreads();
    }

#pragma unroll
    for (int mi = 0; mi < 4; mi++) {
#pragma unroll
        for (int ni = 0; ni < 8; ni++) {
            const int row = m0 + wr + mi * 16 + g;
            const int col = n0 + wc + ni * 8 + t * 2;
            float b0 = 0.f, b1 = 0.f;
            if (bias) { b0 = bias[col]; b1 = bias[col + 1]; }
            float2 v0 = make_float2(acc[mi][ni][0] * alpha + b0, acc[mi][ni][1] * alpha + b1);
            float2 v1 = make_float2(acc[mi][ni][2] * alpha + b0, acc[mi][ni][3] * alpha + b1);
            if (STREAM) {
                __stcs((float2*)&C[(size_t)row * ldc + col], v0);
                __stcs((float2*)&C[(size_t)(row + 8) * ldc + col], v1);
            } else {
                *(float2*)&C[(size_t)row * ldc + col] = v0;
                *(float2*)&C[(size_t)(row + 8) * ldc + col] = v1;
            }
        }
    }
}

// Fused Q/K/V projections: grid.z selects which GEMM.
__global__ __launch_bounds__(128, 2) void qkv_proj(
    const float* __restrict__ query, const float* __restrict__ key_,
    const float* __restrict__ value,
    const float* __restrict__ Wq, const float* __restrict__ Wk,
    const float* __restrict__ Wv)
{
    const int z = blockIdx.z;
    const float* A = (z == 0) ? query : (z == 1) ? key_ : value;
    const float* W = (z == 0) ? Wq : (z == 1) ? Wk : Wv;
    float* C = (z == 0) ? g_Q : (z == 1) ? g_K : g_V;
    gemm_nt_body<EMB, 0>(A, EMB, W, EMB, C, EMB, 1.0f, nullptr);
}

__global__ __launch_bounds__(128, 2) void proj_tf32(
    const float* __restrict__ A, const float* __restrict__ B,
    float* __restrict__ C, const float* __restrict__ bias)
{
    gemm_nt_body<EMB, 0>(A, EMB, B, EMB, C, EMB, 1.0f, bias);
}

// E write is a pure 536MB stream with no L2 reuse -> __stcs epilogue.
__global__ __launch_bounds__(128, 2) void energy_tf32(float* __restrict__ att)
{
    const int z = blockIdx.z;
    const int n = z >> 4, h = z & 15;
    gemm_nt_body<HD, 1>(g_Q + (size_t)n * SEQ * EMB + h * HD, EMB,
                        g_K + (size_t)n * SEQ * EMB + h * HD, EMB,
                        att + (size_t)z * SEQ * SEQ, SEQ, 0.125f, nullptr);
}

// ---------------------------------------------------------------------------
// Row softmax over last dim (1024), in place, with mask[n,k] (-1e20 where 0).
// P write is a 536MB stream (no L2 reuse) -> __stcs.
// ---------------------------------------------------------------------------
__global__ __launch_bounds__(256) void softmax_kernel(
    float* __restrict__ att, const int* __restrict__ mask)
{
    __shared__ float sbuf[8];
    const int row = blockIdx.x;
    const int n = row >> 14;
    float* p = att + (size_t)row * SEQ;
    const int c = threadIdx.x * 4;
    const int* mrow = mask + n * SEQ;

    float4 x = *(const float4*)(p + c);
    if (mrow[c + 0] == 0) x.x = -1e20f;
    if (mrow[c + 1] == 0) x.y = -1e20f;
    if (mrow[c + 2] == 0) x.z = -1e20f;
    if (mrow[c + 3] == 0) x.w = -1e20f;

    float m = fmaxf(fmaxf(x.x, x.y), fmaxf(x.z, x.w));
#pragma unroll
    for (int o = 16; o; o >>= 1) m = fmaxf(m, __shfl_xor_sync(0xffffffffu, m, o));
    if ((threadIdx.x & 31) == 0) sbuf[threadIdx.x >> 5] = m;
    __syncthreads();
    m = sbuf[0];
#pragma unroll
    for (int i = 1; i < 8; i++) m = fmaxf(m, sbuf[i]);

    float4 e;
    e.x = __expf(x.x - m);
    e.y = __expf(x.y - m);
    e.z = __expf(x.z - m);
    e.w = __expf(x.w - m);
    float s = (e.x + e.y) + (e.z + e.w);
#pragma unroll
    for (int o = 16; o; o >>= 1) s += __shfl_xor_sync(0xffffffffu, s, o);
    __syncthreads();
    if ((threadIdx.x & 31) == 0) sbuf[threadIdx.x >> 5] = s;
    __syncthreads();
    s = 0.f;
#pragma unroll
    for (int i = 0; i < 8; i++) s += sbuf[i];

    const float inv = 1.0f / s;
    e.x *= inv; e.y *= inv; e.z *= inv; e.w *= inv;
    __stcs((float4*)(p + c), e);
}

// ---------------------------------------------------------------------------
// att*V (NN): per z = n*16+h,  C[1024,64] = P[1024,1024] @ V[1024,64]
// CTA 128x64, warp tile 64x32. A staged row-major [q][k]; V transposed into
// [n][k] at staging so B fragments also come from ldmatrix.
// 3 CTAs/SM (150 regs fits <=170; 31KB smem x3 fits) -> 12 warps/SM.
// ---------------------------------------------------------------------------
__global__ __launch_bounds__(128, 3) void attv_tf32(const float* __restrict__ att)
{
    const int z = blockIdx.z;
    const int n = z >> 4, h = z & 15;
    const float* A = att + (size_t)z * SEQ * SEQ;
    const float* B = g_V + (size_t)n * SEQ * EMB + h * HD;
    float* C = g_O + (size_t)n * SEQ * EMB + h * HD;

    __shared__ unsigned As[2][128 * SROW];
    __shared__ unsigned Bs[2][64 * SROW];

    const int tid  = threadIdx.x;
    const int m0   = blockIdx.y * 128;
    const int warp = tid >> 5;
    const int lane = tid & 31;
    const int wr   = (warp >> 1) * 64;
    const int wc   = (warp & 1) * 32;
    const int g    = lane >> 2;
    const int t    = lane & 3;

    const uint32_t abase[2] = { smem_u32(&As[0][0]), smem_u32(&As[1][0]) };
    const uint32_t bbase[2] = { smem_u32(&Bs[0][0]), smem_u32(&Bs[1][0]) };

    const int lrow8 = ((lane >> 3) & 1) * 8 + (lane & 7);
    const int ljc   = lane >> 4;
    uint32_t aoff[2][4], boff[2][2];
#pragma unroll
    for (int kkc = 0; kkc < 2; kkc++) {
#pragma unroll
        for (int i = 0; i < 4; i++)
            aoff[kkc][i] = frag_off(wr + i * 16 + lrow8, kkc * 2 + ljc);
#pragma unroll
        for (int p = 0; p < 2; p++)
            boff[kkc][p] = frag_off(wc + p * 16 + lrow8, kkc * 2 + ljc);
    }

    float acc[4][4][4] = {};

    const int srow = tid;
    const float* Ap = A + (size_t)(m0 + srow) * SEQ;
    const int schunkx = (srow >> 3) & 3;
    // B staging: 2 float4 per thread; k = bk (+8), n cols bnc..bnc+3
    const int bk  = tid >> 4;            // 0..7
    const int bnc = (tid & 15) * 4;      // 0..60

    float4 av[4], bvv[2];
    auto ldtile = [&](int kt) {
#pragma unroll
        for (int j = 0; j < 4; j++)
            av[j] = *(const float4*)(Ap + kt * 16 + j * 4);
#pragma unroll
        for (int i = 0; i < 2; i++)
            bvv[i] = *(const float4*)(B + (size_t)(kt * 16 + bk + i * 8) * EMB + bnc);
    };
    auto sttile = [&](int buf) {
#pragma unroll
        for (int j = 0; j < 4; j++) {
            const int chunk = j ^ schunkx;
            uint4 at = make_uint4(f2tf(av[j].x), f2tf(av[j].y), f2tf(av[j].z), f2tf(av[j].w));
            *(uint4*)&As[buf][srow * SROW + chunk * 4] = at;
        }
#pragma unroll
        for (int i = 0; i < 2; i++) {
            const int k = bk + i * 8;
            const int jc = k >> 2, kw = k & 3;
            const float* v4 = (const float*)&bvv[i];
#pragma unroll
            for (int c = 0; c < 4; c++) {
                const int nrow = bnc + c;
                const int chunk = jc ^ ((nrow >> 3) & 3);
                Bs[buf][nrow * SROW + chunk * 4 + kw] = f2tf(v4[c]);
            }
        }
    };

    ldtile(0);
    sttile(0);
    __syncthreads();

    const int NT = SEQ / 16;
#pragma unroll 1
    for (int kt = 0; kt < NT; kt++) {
        const int buf = kt & 1;
        if (kt + 1 < NT) ldtile(kt + 1);

#pragma unroll
        for (int kkc = 0; kkc < 2; kkc++) {
            unsigned af[4][4], bf[4][2];
#pragma unroll
            for (int mi = 0; mi < 4; mi++)
                ldsm4(af[mi][0], af[mi][1], af[mi][2], af[mi][3],
                      abase[buf] + aoff[kkc][mi]);
#pragma unroll
            for (int p = 0; p < 2; p++) {
                unsigned r0, r1, r2, r3;
                ldsm4(r0, r1, r2, r3, bbase[buf] + boff[kkc][p]);
                bf[2 * p][0] = r0; bf[2 * p + 1][0] = r1;
                bf[2 * p][1] = r2; bf[2 * p + 1][1] = r3;
            }
#pragma unroll
            for (int mi = 0; mi < 4; mi++)
#pragma unroll
                for (int ni = 0; ni < 4; ni++)
                    mma_tf32(acc[mi][ni], af[mi], bf[ni]);
        }

        if (kt + 1 < NT) sttile(buf ^ 1);
        __syncthreads();
    }

#pragma unroll
    for (int mi = 0; mi < 4; mi++) {
#pragma unroll
        for (int ni = 0; ni < 4; ni++) {
            const int row = m0 + wr + mi * 16 + g;
            const int col = wc + ni * 8 + t * 2;
            *(float2*)&C[(size_t)row * EMB + col] =
                make_float2(acc[mi][ni][0], acc[mi][ni][1]);
            *(float2*)&C[(size_t)(row + 8) * EMB + col] =
                make_float2(acc[mi][ni][2], acc[mi][ni][3]);
        }
    }
}

// ---------------------------------------------------------------------------
extern "C" void kernel_launch(void* const* d_in, const int* in_sizes, int n_in,
                              void* d_out, int out_size)
{
    const float* value = (const float*)d_in[0];
    const float* key_  = (const float*)d_in[1];
    const float* query = (const float*)d_in[2];
    const int*   mask  = (const int*)d_in[3];
    const float* Wv    = (const float*)d_in[4];
    const float* Wk    = (const float*)d_in[5];
    const float* Wq    = (const float*)d_in[6];
    const float* Wo    = (const float*)d_in[7];
    const float* bo    = (const float*)d_in[8];

    float* out = (float*)d_out;                 // [8,1024,1024]
    float* att = out + OUT_ELEMS;               // [8,16,1024,1024]

    float* op;
    cudaGetSymbolAddress((void**)&op, g_O);

    dim3 blk(128);

    qkv_proj<<<dim3(EMB / 128, ROWS / 128, 3), blk>>>(query, key_, value, Wq, Wk, Wv);
    energy_tf32<<<dim3(SEQ / 128, SEQ / 128, NB * HEADS), blk>>>(att);
    softmax_kernel<<<NB * HEADS * SEQ, 256>>>(att, mask);
    attv_tf32<<<dim3(1, SEQ / 128, NB * HEADS), blk>>>(att);
    proj_tf32<<<dim3(EMB / 128, ROWS / 128), blk>>>(op, Wo, out, bo);
}

// round 17
// speedup vs baseline: 1.1916x; 1.1244x over previous
#include <cuda_runtime.h>
#include <cuda_fp16.h>
#include <math.h>
#include <stdint.h>

#define EMB 1024
#define SEQ 1024
#define NB 8
#define HEADS 16
#define HD 64
#define ROWS (NB * SEQ)                  // 8192
#define OUT_ELEMS ((size_t)ROWS * EMB)   // 8388608
#define SROW 20                          // smem words per row (80B, 16B-aligned)

// Scratch (static device globals; no runtime allocation allowed)
__device__ float g_Q[ROWS * EMB];
__device__ float g_K[ROWS * EMB];
__device__ float g_V[ROWS * EMB];
__device__ float g_O[ROWS * EMB];

// ---------------------------------------------------------------------------
// helpers
// ---------------------------------------------------------------------------
__device__ __forceinline__ unsigned f2h2(float lo, float hi) {
    __half2 h = __floats2half2_rn(lo, hi);   // .x (lo float) -> low 16 bits
    return *(unsigned*)&h;
}

// fp16 m16n8k16, fp32 accumulate
__device__ __forceinline__ void mma_f16(float* c, const unsigned* a, const unsigned* b) {
    asm volatile(
        "mma.sync.aligned.m16n8k16.row.col.f32.f16.f16.f32 "
        "{%0,%1,%2,%3},{%4,%5,%6,%7},{%8,%9},{%0,%1,%2,%3};\n"
        : "+f"(c[0]), "+f"(c[1]), "+f"(c[2]), "+f"(c[3])
        : "r"(a[0]), "r"(a[1]), "r"(a[2]), "r"(a[3]),
          "r"(b[0]), "r"(b[1]));
}

__device__ __forceinline__ uint32_t smem_u32(const void* p) {
    uint32_t a;
    asm("{ .reg .u64 t; cvta.to.shared.u64 t, %1; cvt.u32.u64 %0, t; }"
        : "=r"(a) : "l"(p));
    return a;
}

__device__ __forceinline__ void ldsm4(unsigned& r0, unsigned& r1, unsigned& r2,
                                      unsigned& r3, uint32_t addr) {
    asm volatile("ldmatrix.sync.aligned.m8n8.x4.shared.b16 {%0,%1,%2,%3}, [%4];"
                 : "=r"(r0), "=r"(r1), "=r"(r2), "=r"(r3) : "r"(addr));
}

// byte offset of the 16B chunk jc (8 halves: k = jc*8 .. jc*8+7) of row `row`
__device__ __forceinline__ uint32_t frag_off(int row, int jc) {
    const int chunk = jc ^ ((row >> 3) & 3);
    return (uint32_t)((row * SROW + chunk * 4) * 4);
}

// ---------------------------------------------------------------------------
// NT GEMM: C = alpha * A(row-major,lda) @ B(row-major,ldb)^T + bias
// CTA 128x128, 128 thr (4 warps), warp tile 64x64, BK=16 (one k16 mma step),
// double-buffered. smem rows hold 16 halves in 2 swizzled 16B chunks;
// fragments via ldmatrix.x4 (conflict-free). STREAM=1 -> __stcs epilogue.
// ---------------------------------------------------------------------------
template <int KDIM, int STREAM>
__device__ __forceinline__ void gemm_nt_body(
    const float* __restrict__ A, int lda,
    const float* __restrict__ B, int ldb,
    float* __restrict__ C, int ldc,
    float alpha, const float* __restrict__ bias)
{
    __shared__ unsigned As[2][128 * SROW];
    __shared__ unsigned Bs[2][128 * SROW];

    const int tid  = threadIdx.x;
    const int m0   = blockIdx.y * 128;
    const int n0   = blockIdx.x * 128;
    const int warp = tid >> 5;
    const int lane = tid & 31;
    const int wr   = (warp >> 1) * 64;
    const int wc   = (warp & 1) * 64;
    const int g    = lane >> 2;
    const int t    = lane & 3;

    const uint32_t abase[2] = { smem_u32(&As[0][0]), smem_u32(&As[1][0]) };
    const uint32_t bbase[2] = { smem_u32(&Bs[0][0]), smem_u32(&Bs[1][0]) };

    // ldmatrix pointers: lanes 0-7 rows+0..7/chunk0, 8-15 rows+8..15/chunk0,
    // 16-23 rows/chunk1, 24-31 rows+8/chunk1 -> regs = a0,a1,a2,a3 of k16 frag
    const int lrow8 = ((lane >> 3) & 1) * 8 + (lane & 7);
    const int ljc   = lane >> 4;                     // 0 or 1
    uint32_t aoff[4], boff[4];
#pragma unroll
    for (int i = 0; i < 4; i++) {
        aoff[i] = frag_off(wr + i * 16 + lrow8, ljc);
        boff[i] = frag_off(wc + i * 16 + lrow8, ljc);
    }

    float acc[4][8][4] = {};

    const int srow = tid;                            // staging row 0..127
    const float* Ap = A + (size_t)(m0 + srow) * lda;
    const float* Bp = B + (size_t)(n0 + srow) * ldb;
    const int schunkx = (srow >> 3) & 3;

    float4 av[4], bv[4];
    auto ldtile = [&](int kt) {
#pragma unroll
        for (int j = 0; j < 4; j++) {
            av[j] = *(const float4*)(Ap + kt * 16 + j * 4);
            bv[j] = *(const float4*)(Bp + kt * 16 + j * 4);
        }
    };
    auto sttile = [&](int buf) {
#pragma unroll
        for (int j = 0; j < 2; j++) {                 // chunk j: halves k=j*8..j*8+7
            const int chunk = j ^ schunkx;
            uint4 at = make_uint4(f2h2(av[2*j].x, av[2*j].y),   f2h2(av[2*j].z, av[2*j].w),
                                  f2h2(av[2*j+1].x, av[2*j+1].y), f2h2(av[2*j+1].z, av[2*j+1].w));
            uint4 bt = make_uint4(f2h2(bv[2*j].x, bv[2*j].y),   f2h2(bv[2*j].z, bv[2*j].w),
                                  f2h2(bv[2*j+1].x, bv[2*j+1].y), f2h2(bv[2*j+1].z, bv[2*j+1].w));
            *(uint4*)&As[buf][srow * SROW + chunk * 4] = at;
            *(uint4*)&Bs[buf][srow * SROW + chunk * 4] = bt;
        }
    };

    ldtile(0);
    sttile(0);
    __syncthreads();

    const int NT = KDIM / 16;
#pragma unroll 1
    for (int kt = 0; kt < NT; kt++) {
        const int buf = kt & 1;
        if (kt + 1 < NT) ldtile(kt + 1);

        {
            unsigned af[4][4], bf[8][2];
#pragma unroll
            for (int mi = 0; mi < 4; mi++)
                ldsm4(af[mi][0], af[mi][1], af[mi][2], af[mi][3],
                      abase[buf] + aoff[mi]);
#pragma unroll
            for (int p = 0; p < 4; p++) {
                unsigned r0, r1, r2, r3;
                ldsm4(r0, r1, r2, r3, bbase[buf] + boff[p]);
                bf[2 * p][0] = r0; bf[2 * p + 1][0] = r1;
                bf[2 * p][1] = r2; bf[2 * p + 1][1] = r3;
            }
#pragma unroll
            for (int mi = 0; mi < 4; mi++)
#pragma unroll
                for (int ni = 0; ni < 8; ni++)
                    mma_f16(acc[mi][ni], af[mi], bf[ni]);
        }

        if (kt + 1 < NT) sttile(buf ^ 1);
        __syncthreads();
    }

#pragma unroll
    for (int mi = 0; mi < 4; mi++) {
#pragma unroll
        for (int ni = 0; ni < 8; ni++) {
            const int row = m0 + wr + mi * 16 + g;
            const int col = n0 + wc + ni * 8 + t * 2;
            float b0 = 0.f, b1 = 0.f;
            if (bias) { b0 = bias[col]; b1 = bias[col + 1]; }
            float2 v0 = make_float2(acc[mi][ni][0] * alpha + b0, acc[mi][ni][1] * alpha + b1);
            float2 v1 = make_float2(acc[mi][ni][2] * alpha + b0, acc[mi][ni][3] * alpha + b1);
            if (STREAM) {
                __stcs((float2*)&C[(size_t)row * ldc + col], v0);
                __stcs((float2*)&C[(size_t)(row + 8) * ldc + col], v1);
            } else {
                *(float2*)&C[(size_t)row * ldc + col] = v0;
                *(float2*)&C[(size_t)(row + 8) * ldc + col] = v1;
            }
        }
    }
}

// Fused Q/K/V projections: grid.z selects which GEMM.
__global__ __launch_bounds__(128, 2) void qkv_proj(
    const float* __restrict__ query, const float* __restrict__ key_,
    const float* __restrict__ value,
    const float* __restrict__ Wq, const float* __restrict__ Wk,
    const float* __restrict__ Wv)
{
    const int z = blockIdx.z;
    const float* A = (z == 0) ? query : (z == 1) ? key_ : value;
    const float* W = (z == 0) ? Wq : (z == 1) ? Wk : Wv;
    float* C = (z == 0) ? g_Q : (z == 1) ? g_K : g_V;
    gemm_nt_body<EMB, 0>(A, EMB, W, EMB, C, EMB, 1.0f, nullptr);
}

__global__ __launch_bounds__(128, 2) void proj_tf32(
    const float* __restrict__ A, const float* __restrict__ B,
    float* __restrict__ C, const float* __restrict__ bias)
{
    gemm_nt_body<EMB, 0>(A, EMB, B, EMB, C, EMB, 1.0f, bias);
}

// E write is a pure 536MB stream with no L2 reuse -> __stcs epilogue.
__global__ __launch_bounds__(128, 2) void energy_tf32(float* __restrict__ att)
{
    const int z = blockIdx.z;
    const int n = z >> 4, h = z & 15;
    gemm_nt_body<HD, 1>(g_Q + (size_t)n * SEQ * EMB + h * HD, EMB,
                        g_K + (size_t)n * SEQ * EMB + h * HD, EMB,
                        att + (size_t)z * SEQ * SEQ, SEQ, 0.125f, nullptr);
}

// ---------------------------------------------------------------------------
// Row softmax over last dim (1024), in place, with mask[n,k] (-1e20 where 0).
// P write is a 536MB stream (no L2 reuse) -> __stcs.
// ---------------------------------------------------------------------------
__global__ __launch_bounds__(256) void softmax_kernel(
    float* __restrict__ att, const int* __restrict__ mask)
{
    __shared__ float sbuf[8];
    const int row = blockIdx.x;
    const int n = row >> 14;
    float* p = att + (size_t)row * SEQ;
    const int c = threadIdx.x * 4;
    const int* mrow = mask + n * SEQ;

    float4 x = *(const float4*)(p + c);
    if (mrow[c + 0] == 0) x.x = -1e20f;
    if (mrow[c + 1] == 0) x.y = -1e20f;
    if (mrow[c + 2] == 0) x.z = -1e20f;
    if (mrow[c + 3] == 0) x.w = -1e20f;

    float m = fmaxf(fmaxf(x.x, x.y), fmaxf(x.z, x.w));
#pragma unroll
    for (int o = 16; o; o >>= 1) m = fmaxf(m, __shfl_xor_sync(0xffffffffu, m, o));
    if ((threadIdx.x & 31) == 0) sbuf[threadIdx.x >> 5] = m;
    __syncthreads();
    m = sbuf[0];
#pragma unroll
    for (int i = 1; i < 8; i++) m = fmaxf(m, sbuf[i]);

    float4 e;
    e.x = __expf(x.x - m);
    e.y = __expf(x.y - m);
    e.z = __expf(x.z - m);
    e.w = __expf(x.w - m);
    float s = (e.x + e.y) + (e.z + e.w);
#pragma unroll
    for (int o = 16; o; o >>= 1) s += __shfl_xor_sync(0xffffffffu, s, o);
    __syncthreads();
    if ((threadIdx.x & 31) == 0) sbuf[threadIdx.x >> 5] = s;
    __syncthreads();
    s = 0.f;
#pragma unroll
    for (int i = 0; i < 8; i++) s += sbuf[i];

    const float inv = 1.0f / s;
    e.x *= inv; e.y *= inv; e.z *= inv; e.w *= inv;
    __stcs((float4*)(p + c), e);
}

// ---------------------------------------------------------------------------
// att*V (NN): per z = n*16+h,  C[1024,64] = P[1024,1024] @ V[1024,64]
// CTA 128x64, warp tile 64x32, BK=16 (one k16 step), fp16 operands.
// A staged [q][k] halves; V transposed into [n][k] halves at staging.
// ---------------------------------------------------------------------------
__global__ __launch_bounds__(128, 3) void attv_tf32(const float* __restrict__ att)
{
    const int z = blockIdx.z;
    const int n = z >> 4, h = z & 15;
    const float* A = att + (size_t)z * SEQ * SEQ;
    const float* B = g_V + (size_t)n * SEQ * EMB + h * HD;
    float* C = g_O + (size_t)n * SEQ * EMB + h * HD;

    __shared__ unsigned As[2][128 * SROW];
    __shared__ unsigned Bs[2][64 * SROW];

    const int tid  = threadIdx.x;
    const int m0   = blockIdx.y * 128;
    const int warp = tid >> 5;
    const int lane = tid & 31;
    const int wr   = (warp >> 1) * 64;
    const int wc   = (warp & 1) * 32;
    const int g    = lane >> 2;
    const int t    = lane & 3;

    const uint32_t abase[2] = { smem_u32(&As[0][0]), smem_u32(&As[1][0]) };
    const uint32_t bbase[2] = { smem_u32(&Bs[0][0]), smem_u32(&Bs[1][0]) };

    const int lrow8 = ((lane >> 3) & 1) * 8 + (lane & 7);
    const int ljc   = lane >> 4;
    uint32_t aoff[4], boff[2];
#pragma unroll
    for (int i = 0; i < 4; i++)
        aoff[i] = frag_off(wr + i * 16 + lrow8, ljc);
#pragma unroll
    for (int p = 0; p < 2; p++)
        boff[p] = frag_off(wc + p * 16 + lrow8, ljc);

    float acc[4][4][4] = {};

    const int srow = tid;
    const float* Ap = A + (size_t)(m0 + srow) * SEQ;
    const int schunkx = (srow >> 3) & 3;
    // B staging: 2 float4 per thread; k = bk (+8), n cols bnc..bnc+3
    const int bk  = tid >> 4;            // 0..7
    const int bnc = (tid & 15) * 4;      // 0..60

    float4 av[4], bvv[2];
    auto ldtile = [&](int kt) {
#pragma unroll
        for (int j = 0; j < 4; j++)
            av[j] = *(const float4*)(Ap + kt * 16 + j * 4);
#pragma unroll
        for (int i = 0; i < 2; i++)
            bvv[i] = *(const float4*)(B + (size_t)(kt * 16 + bk + i * 8) * EMB + bnc);
    };
    auto sttile = [&](int buf) {
#pragma unroll
        for (int j = 0; j < 2; j++) {
            const int chunk = j ^ schunkx;
            uint4 at = make_uint4(f2h2(av[2*j].x, av[2*j].y),   f2h2(av[2*j].z, av[2*j].w),
                                  f2h2(av[2*j+1].x, av[2*j+1].y), f2h2(av[2*j+1].z, av[2*j+1].w));
            *(uint4*)&As[buf][srow * SROW + chunk * 4] = at;
        }
        __half* bh = (__half*)&Bs[buf][0];
#pragma unroll
        for (int i = 0; i < 2; i++) {
            const int k = bk + i * 8;                 // 0..15
            const int cb = k >> 3;                    // source chunk (0/1)
            const int off = k & 7;
            const float* v4 = (const float*)&bvv[i];
#pragma unroll
            for (int c = 0; c < 4; c++) {
                const int nrow = bnc + c;
                const int chunk = cb ^ ((nrow >> 3) & 3);
                bh[nrow * (SROW * 2) + chunk * 8 + off] = __float2half_rn(v4[c]);
            }
        }
    };

    ldtile(0);
    sttile(0);
    __syncthreads();

    const int NT = SEQ / 16;
#pragma unroll 1
    for (int kt = 0; kt < NT; kt++) {
        const int buf = kt & 1;
        if (kt + 1 < NT) ldtile(kt + 1);

        {
            unsigned af[4][4], bf[4][2];
#pragma unroll
            for (int mi = 0; mi < 4; mi++)
                ldsm4(af[mi][0], af[mi][1], af[mi][2], af[mi][3],
                      abase[buf] + aoff[mi]);
#pragma unroll
            for (int p = 0; p < 2; p++) {
                unsigned r0, r1, r2, r3;
                ldsm4(r0, r1, r2, r3, bbase[buf] + boff[p]);
                bf[2 * p][0] = r0; bf[2 * p + 1][0] = r1;
                bf[2 * p][1] = r2; bf[2 * p + 1][1] = r3;
            }
#pragma unroll
            for (int mi = 0; mi < 4; mi++)
#pragma unroll
                for (int ni = 0; ni < 4; ni++)
                    mma_f16(acc[mi][ni], af[mi], bf[ni]);
        }

        if (kt + 1 < NT) sttile(buf ^ 1);
        __syncthreads();
    }

#pragma unroll
    for (int mi = 0; mi < 4; mi++) {
#pragma unroll
        for (int ni = 0; ni < 4; ni++) {
            const int row = m0 + wr + mi * 16 + g;
            const int col = wc + ni * 8 + t * 2;
            *(float2*)&C[(size_t)row * EMB + col] =
                make_float2(acc[mi][ni][0], acc[mi][ni][1]);
            *(float2*)&C[(size_t)(row + 8) * EMB + col] =
                make_float2(acc[mi][ni][2], acc[mi][ni][3]);
        }
    }
}

// ---------------------------------------------------------------------------
extern "C" void kernel_launch(void* const* d_in, const int* in_sizes, int n_in,
                              void* d_out, int out_size)
{
    const float* value = (const float*)d_in[0];
    const float* key_  = (const float*)d_in[1];
    const float* query = (const float*)d_in[2];
    const int*   mask  = (const int*)d_in[3];
    const float* Wv    = (const float*)d_in[4];
    const float* Wk    = (const float*)d_in[5];
    const float* Wq    = (const float*)d_in[6];
    const float* Wo    = (const float*)d_in[7];
    const float* bo    = (const float*)d_in[8];

    float* out = (float*)d_out;                 // [8,1024,1024]
    float* att = out + OUT_ELEMS;               // [8,16,1024,1024]

    float* op;
    cudaGetSymbolAddress((void**)&op, g_O);

    dim3 blk(128);

    qkv_proj<<<dim3(EMB / 128, ROWS / 128, 3), blk>>>(query, key_, value, Wq, Wk, Wv);
    energy_tf32<<<dim3(SEQ / 128, SEQ / 128, NB * HEADS), blk>>>(att);
    softmax_kernel<<<NB * HEADS * SEQ, 256>>>(att, mask);
    attv_tf32<<<dim3(1, SEQ / 128, NB * HEADS), blk>>>(att);
    proj_tf32<<<dim3(EMB / 128, ROWS / 128), blk>>>(op, Wo, out, bo);
}